// round 6
// baseline (speedup 1.0000x reference)
#include <cuda_runtime.h>
#include <cuda_fp16.h>
#include <cstdint>

#define DI __device__ __forceinline__

// ---------------------------------------------------------------------------
// Problem constants
// ---------------------------------------------------------------------------
#define BATCH_  8192L
#define WTOT_   41943040L      // 4096*1024 + 4096*4096*2 + 1024*4096
#define HBUF_   33554432L      // 8192*4096

// GEMM tiling
#define BM 256
#define BN 128
#define BK 32                      // halves per K-chunk
#define STAGES 4
#define THREADS 512
#define A_BYTES (BM * 128)         // 32768  (128B row = 64B hi | 64B lo)
#define B_BYTES (BN * 128)         // 16384
#define STAGE_BYTES (A_BYTES + B_BYTES)      // 49152
#define SMEM_BYTES (STAGES * STAGE_BYTES)    // 196608

// ---------------------------------------------------------------------------
// Scratch: __device__ globals (no runtime allocation anywhere)
// ---------------------------------------------------------------------------
__device__ __half g_Whi[WTOT_];
__device__ __half g_Wlo[WTOT_];
__device__ float  g_bias[4 * 4096];
__device__ __half g_hAhi[HBUF_], g_hAlo[HBUF_];
__device__ __half g_hBhi[HBUF_], g_hBlo[HBUF_];

// ---------------------------------------------------------------------------
// Small helpers
// ---------------------------------------------------------------------------
DI uint32_t smem_u32(const void* p) {
    uint32_t a;
    asm("{ .reg .u64 t; cvta.to.shared.u64 t, %1; cvt.u32.u64 %0, t; }"
        : "=r"(a) : "l"(p));
    return a;
}

DI void cp16(uint32_t dst, const void* src) {
    asm volatile("cp.async.cg.shared.global [%0], [%1], 16;"
                 :: "r"(dst), "l"(src));
}

DI void ldsm_x4(uint32_t* r, uint32_t addr) {
    asm volatile("ldmatrix.sync.aligned.m8n8.x4.shared.b16 {%0,%1,%2,%3}, [%4];"
                 : "=r"(r[0]), "=r"(r[1]), "=r"(r[2]), "=r"(r[3]) : "r"(addr));
}

DI void ldsm_x2(uint32_t* r, uint32_t addr) {
    asm volatile("ldmatrix.sync.aligned.m8n8.x2.shared.b16 {%0,%1}, [%2];"
                 : "=r"(r[0]), "=r"(r[1]) : "r"(addr));
}

DI void mma16816(float* d, const uint32_t* a, const uint32_t* b) {
    asm volatile(
        "mma.sync.aligned.m16n8k16.row.col.f32.f16.f16.f32 "
        "{%0,%1,%2,%3}, {%4,%5,%6,%7}, {%8,%9}, {%0,%1,%2,%3};"
        : "+f"(d[0]), "+f"(d[1]), "+f"(d[2]), "+f"(d[3])
        : "r"(a[0]), "r"(a[1]), "r"(a[2]), "r"(a[3]), "r"(b[0]), "r"(b[1]));
}

DI float softplus_f(float s) {
    return (s > 20.0f) ? s : log1pf(expf(s));
}

DI void split2(float v, __half& hi, __half& lo) {
    hi = __float2half_rn(v);
    lo = __float2half_rn(v - __half2float(hi));
}

// ---------------------------------------------------------------------------
// Prep kernels
// ---------------------------------------------------------------------------
__global__ void prep_w(const float* __restrict__ mw, const float* __restrict__ sw,
                       const float* __restrict__ zw, long woff, long n)
{
    long t = (long)blockIdx.x * blockDim.x + threadIdx.x;
    long stride = (long)gridDim.x * blockDim.x;
    for (long e = t * 4; e < n; e += stride * 4) {
        float4 m = *(const float4*)(mw + e);
        float4 s = *(const float4*)(sw + e);
        float4 z = *(const float4*)(zw + e);
        float a0 = m.x + softplus_f(s.x) * z.x;
        float a1 = m.y + softplus_f(s.y) * z.y;
        float a2 = m.z + softplus_f(s.z) * z.z;
        float a3 = m.w + softplus_f(s.w) * z.w;
        __half h0, h1, h2, h3, l0, l1, l2, l3;
        split2(a0, h0, l0); split2(a1, h1, l1);
        split2(a2, h2, l2); split2(a3, h3, l3);
        __half2* ph = (__half2*)(g_Whi + woff + e);
        __half2* pl = (__half2*)(g_Wlo + woff + e);
        ph[0] = __halves2half2(h0, h1); ph[1] = __halves2half2(h2, h3);
        pl[0] = __halves2half2(l0, l1); pl[1] = __halves2half2(l2, l3);
    }
}

__global__ void prep_b(const float* __restrict__ mb, const float* __restrict__ sb,
                       const float* __restrict__ zb, int layer, int n)
{
    int i = blockIdx.x * blockDim.x + threadIdx.x;
    if (i < n)
        g_bias[layer * 4096 + i] = mb[i] + softplus_f(sb[i]) * zb[i];
}

__global__ void prep_x(const float* __restrict__ x, long n)
{
    long t = (long)blockIdx.x * blockDim.x + threadIdx.x;
    long stride = (long)gridDim.x * blockDim.x;
    for (long e = t * 4; e < n; e += stride * 4) {
        float4 v = *(const float4*)(x + e);
        __half h0, h1, h2, h3, l0, l1, l2, l3;
        split2(v.x, h0, l0); split2(v.y, h1, l1);
        split2(v.z, h2, l2); split2(v.w, h3, l3);
        __half2* ph = (__half2*)(g_hAhi + e);
        __half2* pl = (__half2*)(g_hAlo + e);
        ph[0] = __halves2half2(h0, h1); ph[1] = __halves2half2(h2, h3);
        pl[0] = __halves2half2(l0, l1); pl[1] = __halves2half2(l2, l3);
    }
}

// ---------------------------------------------------------------------------
// Stage loader (512 threads): A = 256 rows x 128B, B = 128 rows x 128B.
// Row layout: 128B = [hi k0..31 (64B) | lo k0..31 (64B)], 16B granules XOR'd
// with ((row&7)<<4).  Per thread: 4 cp16 for A, 2 cp16 for B = 96B.
// ---------------------------------------------------------------------------
DI void load_stage(uint32_t stageBase, long kc,
                   const __half* aHiP, const __half* aLoP,
                   const __half* bHiP, const __half* bLoP,
                   uint32_t aOff0, uint32_t aOff1, uint32_t bOff)
{
    cp16(stageBase + aOff0,         aHiP + kc);
    cp16(stageBase + (aOff0 ^ 64u), aLoP + kc);
    cp16(stageBase + aOff1,         aHiP + kc + 8);
    cp16(stageBase + (aOff1 ^ 64u), aLoP + kc + 8);
    cp16(stageBase + bOff,          bHiP + kc);
    cp16(stageBase + (bOff ^ 64u),  bLoP + kc);
    asm volatile("cp.async.commit_group;" ::: "memory");
}

// ---------------------------------------------------------------------------
// Split-fp16 GEMM:  O[BM,BN] tile of  H[B,K] @ W[dout,K]^T + bias (+tanh)
// acc = Hhi*Whi + Hhi*Wlo + Hlo*Whi  (fp32 register accumulators)
// 16 warps as 4(m) x 4(n); warp tile 64x32; mma.sync m16n8k16
// Product-type-outer ordering: 4 independent MMAs between accumulator reuse.
// ---------------------------------------------------------------------------
__global__ void __launch_bounds__(THREADS, 1)
gemm_split(int inSel, long woff, int K, int dout, int bOff, int last,
           float* __restrict__ out)
{
    extern __shared__ __align__(128) uint8_t smem_raw[];
    const uint32_t sb = smem_u32(smem_raw);
    const int tid  = threadIdx.x;
    const int lane = tid & 31;
    const int wid  = tid >> 5;
    const int wm   = wid >> 2;      // 0..3
    const int wn   = wid & 3;       // 0..3

    const __half* Hhi = inSel ? g_hBhi : g_hAhi;
    const __half* Hlo = inSel ? g_hBlo : g_hAlo;
    __half* Ohi = inSel ? g_hAhi : g_hBhi;
    __half* Olo = inSel ? g_hAlo : g_hBlo;
    const __half* Whi = g_Whi + woff;
    const __half* Wlo = g_Wlo + woff;

    const long rowW = (long)blockIdx.x * BN;   // output-col base (x fastest: L2 reuse)
    const long rowH = (long)blockIdx.y * BM;   // batch-row base

    // ---- loader thread mapping (conflict-free smem writes) ----
    const int ar  = tid >> 1;                 // 0..255
    const int ah2 = tid & 1;                  // granule pair select
    const uint32_t aswz  = (uint32_t)((ar & 7) << 4);
    const uint32_t aOff0 = (uint32_t)ar * 128u + (((uint32_t)(2 * ah2) * 16u) ^ aswz);
    const uint32_t aOff1 = (uint32_t)ar * 128u + (((uint32_t)(2 * ah2 + 1) * 16u) ^ aswz);
    const __half* aHiP = Hhi + (rowH + ar) * (long)K + ah2 * 16;
    const __half* aLoP = Hlo + (rowH + ar) * (long)K + ah2 * 16;

    const int br = tid >> 2;                  // 0..127
    const int bc = tid & 3;                   // granule 0..3
    const uint32_t bOffD = (uint32_t)A_BYTES + (uint32_t)br * 128u +
                           (((uint32_t)bc * 16u) ^ (uint32_t)((br & 7) << 4));
    const __half* bHiP = Whi + (rowW + br) * (long)K + bc * 8;
    const __half* bLoP = Wlo + (rowW + br) * (long)K + bc * 8;

    // ---- ldmatrix per-lane address bases (offset within stage; kk=0, hi) ----
    uint32_t aAddr[4];
#pragma unroll
    for (int mf = 0; mf < 4; ++mf) {
        uint32_t r = (uint32_t)(wm * 64 + mf * 16 + (lane & 15));
        uint32_t c = (uint32_t)((lane >> 4) << 4);
        aAddr[mf] = r * 128u + (c ^ ((r & 7u) << 4));
    }
    uint32_t bAddr[4];
#pragma unroll
    for (int nf = 0; nf < 4; ++nf) {
        uint32_t r = (uint32_t)(wn * 32 + nf * 8 + (lane & 7));
        uint32_t c = (uint32_t)(((lane >> 3) & 1) << 4);
        bAddr[nf] = (uint32_t)A_BYTES + r * 128u + (c ^ ((r & 7u) << 4));
    }

    float acc[4][4][4];
#pragma unroll
    for (int mf = 0; mf < 4; ++mf)
#pragma unroll
        for (int nf = 0; nf < 4; ++nf)
#pragma unroll
            for (int q = 0; q < 4; ++q) acc[mf][nf][q] = 0.0f;

    const int nIter = K / BK;

    // prologue: 3 stages in flight
    load_stage(sb + 0u * STAGE_BYTES, 0L * BK, aHiP, aLoP, bHiP, bLoP, aOff0, aOff1, bOffD);
    load_stage(sb + 1u * STAGE_BYTES, 1L * BK, aHiP, aLoP, bHiP, bLoP, aOff0, aOff1, bOffD);
    load_stage(sb + 2u * STAGE_BYTES, 2L * BK, aHiP, aLoP, bHiP, bLoP, aOff0, aOff1, bOffD);

    for (int it = 0; it < nIter; ++it) {
        asm volatile("cp.async.wait_group 2;" ::: "memory");
        __syncthreads();

        if (it + 3 < nIter)
            load_stage(sb + (uint32_t)((it + 3) & 3) * STAGE_BYTES, (long)(it + 3) * BK,
                       aHiP, aLoP, bHiP, bLoP, aOff0, aOff1, bOffD);
        else
            asm volatile("cp.async.commit_group;" ::: "memory");

        const uint32_t stg = sb + (uint32_t)(it & 3) * STAGE_BYTES;

#pragma unroll
        for (int kk = 0; kk < 2; ++kk) {
            const uint32_t kx = (uint32_t)kk * 32u;
            uint32_t ah[4][4], al[4][4];
#pragma unroll
            for (int mf = 0; mf < 4; ++mf) {
                ldsm_x4(ah[mf], stg + (aAddr[mf] ^ kx));
                ldsm_x4(al[mf], stg + (aAddr[mf] ^ kx ^ 64u));
            }
            uint32_t bh[4][2], bl[4][2];
#pragma unroll
            for (int nf = 0; nf < 4; ++nf) {
                ldsm_x2(bh[nf], stg + (bAddr[nf] ^ kx));
                ldsm_x2(bl[nf], stg + (bAddr[nf] ^ kx ^ 64u));
            }
            // product-type outer, mf inner: 4 independent MMAs between
            // consecutive writes to the same accumulator
#pragma unroll
            for (int nf = 0; nf < 4; ++nf) {
#pragma unroll
                for (int mf = 0; mf < 4; ++mf) mma16816(acc[mf][nf], ah[mf], bh[nf]);
#pragma unroll
                for (int mf = 0; mf < 4; ++mf) mma16816(acc[mf][nf], ah[mf], bl[nf]);
#pragma unroll
                for (int mf = 0; mf < 4; ++mf) mma16816(acc[mf][nf], al[mf], bh[nf]);
            }
        }
    }

    asm volatile("cp.async.wait_group 0;" ::: "memory");

    // ---- epilogue ----
    const int r0 = lane >> 2;
    const int c0 = (lane & 3) * 2;
#pragma unroll
    for (int mf = 0; mf < 4; ++mf) {
#pragma unroll
        for (int nf = 0; nf < 4; ++nf) {
            const long col = rowW + wn * 32 + nf * 8 + c0;
            const float2 bv = *(const float2*)(g_bias + bOff + col);
#pragma unroll
            for (int h = 0; h < 2; ++h) {
                const long m = rowH + wm * 64 + mf * 16 + r0 + h * 8;
                float v0 = acc[mf][nf][h * 2 + 0] + bv.x;
                float v1 = acc[mf][nf][h * 2 + 1] + bv.y;
                if (last) {
                    *(float2*)(out + m * dout + col) = make_float2(v0, v1);
                } else {
                    v0 = tanhf(v0); v1 = tanhf(v1);
                    __half h0, l0, h1, l1;
                    split2(v0, h0, l0); split2(v1, h1, l1);
                    *(__half2*)(Ohi + m * dout + col) = __halves2half2(h0, h1);
                    *(__half2*)(Olo + m * dout + col) = __halves2half2(l0, l1);
                }
            }
        }
    }
}

// ---------------------------------------------------------------------------
// Host launcher
// ---------------------------------------------------------------------------
extern "C" void kernel_launch(void* const* d_in, const int* in_sizes, int n_in,
                              void* d_out, int out_size)
{
    (void)in_sizes; (void)n_in; (void)out_size;

    static const int  DIN[4]   = {1024, 4096, 4096, 4096};
    static const int  DOUTL[4] = {4096, 4096, 4096, 1024};
    static const long WOFF[4]  = {0L, 4194304L, 20971520L, 37748736L};

    cudaFuncSetAttribute(gemm_split, cudaFuncAttributeMaxDynamicSharedMemorySize,
                         SMEM_BYTES);

    const float* x = (const float*)d_in[0];
    prep_x<<<512, 256>>>(x, BATCH_ * 1024L);

    for (int j = 0; j < 4; ++j) {
        const float* mw = (const float*)d_in[1 + 6 * j];
        const float* sw = (const float*)d_in[2 + 6 * j];
        const float* zw = (const float*)d_in[3 + 6 * j];
        const float* mb = (const float*)d_in[4 + 6 * j];
        const float* sb = (const float*)d_in[5 + 6 * j];
        const float* zb = (const float*)d_in[6 + 6 * j];
        long n = (long)DOUTL[j] * DIN[j];
        prep_w<<<2048, 256>>>(mw, sw, zw, WOFF[j], n);
        prep_b<<<16, 256>>>(mb, sb, zb, j, DOUTL[j]);
    }

    for (int j = 0; j < 4; ++j) {
        dim3 grid(DOUTL[j] / BN, (int)(BATCH_ / BM));
        gemm_split<<<grid, THREADS, SMEM_BYTES>>>(j & 1, WOFF[j], DIN[j], DOUTL[j],
                                                  j * 4096, (j == 3) ? 1 : 0,
                                                  (float*)d_out);
    }
}